// round 11
// baseline (speedup 1.0000x reference)
#include <cuda_runtime.h>
#include <cuda_fp16.h>
#include <cstdint>
#include <math.h>

#define NB   8
#define NC   1536
#define HWSZ 1024
#define NG   24
#define CPG  64

__device__ __half g_xh[(size_t)NB * NC * HWSZ];   // GN-normalized fp16 tensor

// pack two floats into half2 {lo=a, hi=b}
__device__ __forceinline__ uint32_t packh2(float a, float b) {
    uint32_t r;
    asm("cvt.rn.f16x2.f32 %0, %1, %2;" : "=r"(r) : "f"(b), "f"(a));
    return r;
}

// ---------------------------------------------------------------------------
// Kernel A (fused): per-(b,group) stats + fp16 conversion in one pass.
// ---------------------------------------------------------------------------
__global__ __launch_bounds__(1024)
void gn_fused_kernel(const float* __restrict__ x,
                     const float* __restrict__ w,
                     const float* __restrict__ bs) {
    const int b = blockIdx.x / NG;
    const int g = blockIdx.x % NG;
    const int tid = threadIdx.x;
    const size_t base = ((size_t)b * NC + (size_t)g * CPG) * HWSZ;
    const float4* p4 = (const float4*)(x + base);

    float s0 = 0.f, s1 = 0.f, s2 = 0.f, s3 = 0.f;
    float q0 = 0.f, q1 = 0.f, q2 = 0.f, q3 = 0.f;
    #pragma unroll
    for (int k = 0; k < 4; k++) {
        float4 a = p4[tid + (4 * k + 0) * 1024];
        float4 c = p4[tid + (4 * k + 1) * 1024];
        float4 d = p4[tid + (4 * k + 2) * 1024];
        float4 e = p4[tid + (4 * k + 3) * 1024];
        s0 += a.x + a.y + a.z + a.w;
        q0 += a.x * a.x + a.y * a.y + a.z * a.z + a.w * a.w;
        s1 += c.x + c.y + c.z + c.w;
        q1 += c.x * c.x + c.y * c.y + c.z * c.z + c.w * c.w;
        s2 += d.x + d.y + d.z + d.w;
        q2 += d.x * d.x + d.y * d.y + d.z * d.z + d.w * d.w;
        s3 += e.x + e.y + e.z + e.w;
        q3 += e.x * e.x + e.y * e.y + e.z * e.z + e.w * e.w;
    }
    float s = (s0 + s1) + (s2 + s3);
    float q = (q0 + q1) + (q2 + q3);

    __shared__ float rs[32], rq[32], stat[2];
    __shared__ float sSc[CPG], sSh[CPG];
    #pragma unroll
    for (int off = 16; off > 0; off >>= 1) {
        s += __shfl_xor_sync(0xffffffffu, s, off);
        q += __shfl_xor_sync(0xffffffffu, q, off);
    }
    if ((tid & 31) == 0) { rs[tid >> 5] = s; rq[tid >> 5] = q; }
    __syncthreads();
    if (tid < 32) {
        float ws = rs[tid], wq = rq[tid];
        #pragma unroll
        for (int off = 16; off > 0; off >>= 1) {
            ws += __shfl_xor_sync(0xffffffffu, ws, off);
            wq += __shfl_xor_sync(0xffffffffu, wq, off);
        }
        if (tid == 0) {
            const float inv_n = 1.f / (float)(CPG * HWSZ);
            float mean = ws * inv_n;
            float var  = wq * inv_n - mean * mean;
            stat[0] = mean;
            stat[1] = rsqrtf(var + 1e-5f);
        }
    }
    __syncthreads();
    if (tid < CPG) {
        const float QSC = 0.125f * 1.4426950408889634f;
        float mean = stat[0], rstd = stat[1];
        int c = g * CPG + tid;
        float sc = rstd * w[c];
        float sh = bs[c] - mean * sc;
        if (g % 3 == 1) { sc *= QSC; sh *= QSC; }    // whole group is Q
        sSc[tid] = sc;
        sSh[tid] = sh;
    }
    __syncthreads();

    __half* oh = g_xh + base;
    #pragma unroll
    for (int k = 0; k < 8; k++) {
        int chunk = tid + k * 1024;
        int e = chunk * 8;
        int c = e >> 10;
        float sc = sSc[c], sh = sSh[c];
        float4 v0 = p4[chunk * 2];
        float4 v1 = p4[chunk * 2 + 1];
        uint4 pk;
        pk.x = packh2(v0.x * sc + sh, v0.y * sc + sh);
        pk.y = packh2(v0.z * sc + sh, v0.w * sc + sh);
        pk.z = packh2(v1.x * sc + sh, v1.y * sc + sh);
        pk.w = packh2(v1.z * sc + sh, v1.w * sc + sh);
        *(uint4*)&oh[e] = pk;
    }
}

// ---------------------------------------------------------------------------
// helpers
// ---------------------------------------------------------------------------
__device__ __forceinline__ uint32_t smem_u32(const void* p) {
    uint32_t a;
    asm("{ .reg .u64 t; cvta.to.shared.u64 t, %1; cvt.u32.u64 %0, t; }"
        : "=r"(a) : "l"(p));
    return a;
}
__device__ __forceinline__ float ex2f(float x) {
    float r; asm("ex2.approx.ftz.f32 %0, %1;" : "=f"(r) : "f"(x)); return r;
}
__device__ __forceinline__ void ldsm4(uint32_t* r, uint32_t addr) {
    asm volatile("ldmatrix.sync.aligned.m8n8.x4.shared.b16 {%0,%1,%2,%3}, [%4];"
                 : "=r"(r[0]), "=r"(r[1]), "=r"(r[2]), "=r"(r[3]) : "r"(addr));
}
__device__ __forceinline__ void ldsm4t(uint32_t* r, uint32_t addr) {
    asm volatile("ldmatrix.sync.aligned.m8n8.x4.trans.shared.b16 {%0,%1,%2,%3}, [%4];"
                 : "=r"(r[0]), "=r"(r[1]), "=r"(r[2]), "=r"(r[3]) : "r"(addr));
}
__device__ __forceinline__ void mma16816(float* d, const uint32_t* a,
                                         uint32_t b0, uint32_t b1) {
    asm volatile(
        "mma.sync.aligned.m16n8k16.row.col.f32.f16.f16.f32 "
        "{%0,%1,%2,%3}, {%4,%5,%6,%7}, {%8,%9}, {%0,%1,%2,%3};"
        : "+f"(d[0]), "+f"(d[1]), "+f"(d[2]), "+f"(d[3])
        : "r"(a[0]), "r"(a[1]), "r"(a[2]), "r"(a[3]), "r"(b0), "r"(b1));
}
__device__ __forceinline__ void cp16(uint32_t dst, const void* src) {
    asm volatile("cp.async.cg.shared.global [%0], [%1], 16;"
                 :: "r"(dst), "l"(src) : "memory");
}
__device__ __forceinline__ void cp_commit() {
    asm volatile("cp.async.commit_group;" ::: "memory");
}
template<int N> __device__ __forceinline__ void cp_wait() {
    asm volatile("cp.async.wait_group %0;" :: "n"(N) : "memory");
}

// SMEM layout (bytes):
//   Qs  half[64][136]          @ 0         (17408)
//   4 x { Ks half[64][72] ; Vs half[64][72] }  @ 17408, stride 18432
// Osm float[64][132] (33792B) overlays @0 in the epilogue.
#define QS_OFF   0
#define BUF_OFF  17408
#define BUF_STR  18432
#define SMEM_SZ  91136

// ---------------------------------------------------------------------------
// Kernel B: HMMA flash attention, pair-granularity double buffering:
// ONE barrier per 2 key-tiles (128 keys) so warps free-run across the
// S-MMA / exp / PV-MMA phases of two tiles (cross-warp pipe overlap).
// Per tile, chunk-level pipeline: S(p) ; PV(p-1) ; exp(p).
// grid = (8 q-tiles of 128, 64 bh), 256 threads.
// ---------------------------------------------------------------------------
__global__ __launch_bounds__(256, 2)
void attn_mma(float* __restrict__ out) {
    extern __shared__ char smc[];
    float* Osm = (float*)smc;

    const uint32_t sb = smem_u32(smc);
    const int tid = threadIdx.x;
    const int wid = tid >> 5, lane = tid & 31;
    const int qbase = wid * 16;
    const int bh = blockIdx.y, b = bh >> 3, h = bh & 7;
    const int q0 = blockIdx.x * 128;
    const __half* xh = g_xh + ((size_t)b * NC + (size_t)h * 192) * HWSZ;

    // Q prologue: 64 rows x 256B = 1024 chunks of 16B, 4 per thread.
    {
        #pragma unroll
        for (int k = 0; k < 4; k++) {
            int idx = tid + k * 256;
            int row = idx >> 4, ch = idx & 15;
            cp16(sb + QS_OFF + (uint32_t)(row * 272 + ch * 16),
                 xh + (size_t)(64 + row) * HWSZ + q0 + ch * 8);
        }
        cp_commit();
    }
    // Stage pair 0 (tiles 0,1 -> buffers 0,1).
    #pragma unroll
    for (int t0 = 0; t0 < 2; t0++) {
        uint32_t bufb = sb + BUF_OFF + t0 * BUF_STR;
        #pragma unroll
        for (int k = 0; k < 2; k++) {
            int idx = tid + k * 256;
            int row = idx >> 3, ch = idx & 7;
            cp16(bufb + (uint32_t)(row * 144 + ch * 16),
                 xh + (size_t)row * HWSZ + t0 * 64 + ch * 8);
        }
        #pragma unroll
        for (int k = 0; k < 2; k++) {
            int idx = tid + k * 256;
            int row = idx >> 3, ch = idx & 7;
            cp16(bufb + 9216 + (uint32_t)(row * 144 + ch * 16),
                 xh + (size_t)(128 + row) * HWSZ + t0 * 64 + ch * 8);
        }
    }
    cp_commit();

    cp_wait<1>();          // Q landed (pair 0 may still be in flight)
    __syncthreads();

    // ---- Preload Q fragments (persist across all k-tiles) ----
    uint32_t qf[4][4];
    {
        int crow0 = ((lane & 16) >> 1) + (lane & 7);
        int qcol  = qbase + (lane & 8);
        #pragma unroll
        for (int kc = 0; kc < 4; kc++)
            ldsm4t(qf[kc], sb + QS_OFF + (uint32_t)((kc * 16 + crow0) * 136 + qcol) * 2);
    }

    float o[8][4];
    #pragma unroll
    for (int i = 0; i < 8; i++)
        #pragma unroll
        for (int j = 0; j < 4; j++) o[i][j] = 0.f;
    float l0 = 0.f, l1 = 0.f;

    const uint32_t kfo = (uint32_t)(((lane & 8) + (lane & 7)) * 72 + ((lane & 16) >> 1)) * 2;
    const uint32_t vfo = (uint32_t)((((lane & 16) >> 1) + (lane & 7)) * 72 + (lane & 8)) * 2 + 9216;

    for (int t = 0; t < 8; t++) {
        cp_wait<0>();      // pair t landed
        __syncthreads();   // all warps done with pair t-1's buffers

        // Prefetch pair t+1 into the other buffer half (hidden under compute).
        if (t < 7) {
            #pragma unroll
            for (int s = 0; s < 2; s++) {
                const int ktn = 2 * t + 2 + s;
                const int jn = ktn * 64;
                uint32_t bufb = sb + BUF_OFF + (ktn & 3) * BUF_STR;
                #pragma unroll
                for (int k = 0; k < 2; k++) {
                    int idx = tid + k * 256;
                    int row = idx >> 3, ch = idx & 7;
                    cp16(bufb + (uint32_t)(row * 144 + ch * 16),
                         xh + (size_t)row * HWSZ + jn + ch * 8);
                }
                #pragma unroll
                for (int k = 0; k < 2; k++) {
                    int idx = tid + k * 256;
                    int row = idx >> 3, ch = idx & 7;
                    cp16(bufb + 9216 + (uint32_t)(row * 144 + ch * 16),
                         xh + (size_t)(128 + row) * HWSZ + jn + ch * 8);
                }
            }
            cp_commit();
        }

        // ---- Compute both tiles of the pair (no barrier between) ----
        #pragma unroll
        for (int sub = 0; sub < 2; sub++) {
            const int kt = 2 * t + sub;
            const uint32_t bufb = sb + BUF_OFF + (kt & 3) * BUF_STR;
            const uint32_t kfb = bufb + kfo;
            const uint32_t vfb = bufb + vfo;

            uint32_t pprev[4];      // packed P for chunk p-1
            #pragma unroll
            for (int p = 0; p < 4; p++) {
                // S-MMAs for n-chunk p (16 keys)
                float s0[4] = {0.f, 0.f, 0.f, 0.f};
                float s1[4] = {0.f, 0.f, 0.f, 0.f};
                #pragma unroll
                for (int kc = 0; kc < 4; kc++) {
                    uint32_t kb[4];
                    ldsm4t(kb, kfb + (uint32_t)(kc * 16 * 72 + p * 16) * 2);
                    mma16816(s0, qf[kc], kb[0], kb[1]);
                    mma16816(s1, qf[kc], kb[2], kb[3]);
                }
                // PV-MMAs for chunk p-1 (independent of the S-MMAs above)
                if (p > 0) {
                    const int jc = p - 1;
                    #pragma unroll
                    for (int vp = 0; vp < 4; vp++) {
                        uint32_t vb[4];
                        ldsm4(vb, vfb + (uint32_t)(vp * 16 * 72 + jc * 16) * 2);
                        mma16816(o[2 * vp],     pprev, vb[0], vb[1]);
                        mma16816(o[2 * vp + 1], pprev, vb[2], vb[3]);
                    }
                }
                // exp chunk p
                float a0 = ex2f(s0[0]), a1 = ex2f(s0[1]);
                float a2 = ex2f(s0[2]), a3 = ex2f(s0[3]);
                float b0 = ex2f(s1[0]), b1 = ex2f(s1[1]);
                float b2 = ex2f(s1[2]), b3 = ex2f(s1[3]);
                l0 += a0 + a1 + b0 + b1;
                l1 += a2 + a3 + b2 + b3;
                pprev[0] = packh2(a0, a1);
                pprev[1] = packh2(a2, a3);
                pprev[2] = packh2(b0, b1);
                pprev[3] = packh2(b2, b3);
            }
            // tail: PV for chunk 3
            #pragma unroll
            for (int vp = 0; vp < 4; vp++) {
                uint32_t vb[4];
                ldsm4(vb, vfb + (uint32_t)(vp * 16 * 72 + 3 * 16) * 2);
                mma16816(o[2 * vp],     pprev, vb[0], vb[1]);
                mma16816(o[2 * vp + 1], pprev, vb[2], vb[3]);
            }
        }
    }

    // ---- Epilogue: normalize, stage via SMEM, coalesced store ----
    l0 += __shfl_xor_sync(0xffffffffu, l0, 1);
    l0 += __shfl_xor_sync(0xffffffffu, l0, 2);
    l1 += __shfl_xor_sync(0xffffffffu, l1, 1);
    l1 += __shfl_xor_sync(0xffffffffu, l1, 2);
    float inv0 = 1.f / l0, inv1 = 1.f / l1;

    __syncthreads();       // all warps done with Q/K/V SMEM
    {
        int qa = qbase + (lane >> 2);
        #pragma unroll
        for (int vn = 0; vn < 8; vn++) {
            int vd = vn * 8 + (lane & 3) * 2;
            Osm[vd * 132 + qa]           = o[vn][0] * inv0;
            Osm[(vd + 1) * 132 + qa]     = o[vn][1] * inv0;
            Osm[vd * 132 + qa + 8]       = o[vn][2] * inv1;
            Osm[(vd + 1) * 132 + qa + 8] = o[vn][3] * inv1;
        }
    }
    __syncthreads();

    float* gout = out + ((size_t)(bh * 64)) * HWSZ + q0;
    #pragma unroll
    for (int k = 0; k < 8; k++) {
        int idx = tid + k * 256;
        int vd = idx >> 5, fq = (idx & 31) * 4;
        *(float4*)(gout + (size_t)vd * HWSZ + fq) = *(const float4*)&Osm[vd * 132 + fq];
    }
}

// ---------------------------------------------------------------------------
extern "C" void kernel_launch(void* const* d_in, const int* in_sizes, int n_in,
                              void* d_out, int out_size) {
    const float* x    = (const float*)d_in[0];
    const float* w    = (const float*)d_in[1];
    const float* bias = (const float*)d_in[2];
    float* out = (float*)d_out;

    cudaFuncSetAttribute(attn_mma, cudaFuncAttributeMaxDynamicSharedMemorySize, SMEM_SZ);

    gn_fused_kernel<<<NB * NG, 1024>>>(x, w, bias);
    attn_mma<<<dim3(8, 64), 256, SMEM_SZ>>>(out);
}

// round 12
// speedup vs baseline: 1.0175x; 1.0175x over previous
#include <cuda_runtime.h>
#include <cuda_fp16.h>
#include <cstdint>
#include <math.h>

#define NB   8
#define NC   1536
#define HWSZ 1024
#define NG   24
#define CPG  64

__device__ __half g_xh[(size_t)NB * NC * HWSZ];   // GN-normalized fp16 tensor

// pack two floats into half2 {lo=a, hi=b}
__device__ __forceinline__ uint32_t packh2(float a, float b) {
    uint32_t r;
    asm("cvt.rn.f16x2.f32 %0, %1, %2;" : "=r"(r) : "f"(b), "f"(a));
    return r;
}

// ---------------------------------------------------------------------------
// Kernel A (fused): per-(b,group) stats + fp16 conversion in one pass.
// ---------------------------------------------------------------------------
__global__ __launch_bounds__(1024)
void gn_fused_kernel(const float* __restrict__ x,
                     const float* __restrict__ w,
                     const float* __restrict__ bs) {
    const int b = blockIdx.x / NG;
    const int g = blockIdx.x % NG;
    const int tid = threadIdx.x;
    const size_t base = ((size_t)b * NC + (size_t)g * CPG) * HWSZ;
    const float4* p4 = (const float4*)(x + base);

    float s0 = 0.f, s1 = 0.f, s2 = 0.f, s3 = 0.f;
    float q0 = 0.f, q1 = 0.f, q2 = 0.f, q3 = 0.f;
    #pragma unroll
    for (int k = 0; k < 4; k++) {
        float4 a = p4[tid + (4 * k + 0) * 1024];
        float4 c = p4[tid + (4 * k + 1) * 1024];
        float4 d = p4[tid + (4 * k + 2) * 1024];
        float4 e = p4[tid + (4 * k + 3) * 1024];
        s0 += a.x + a.y + a.z + a.w;
        q0 += a.x * a.x + a.y * a.y + a.z * a.z + a.w * a.w;
        s1 += c.x + c.y + c.z + c.w;
        q1 += c.x * c.x + c.y * c.y + c.z * c.z + c.w * c.w;
        s2 += d.x + d.y + d.z + d.w;
        q2 += d.x * d.x + d.y * d.y + d.z * d.z + d.w * d.w;
        s3 += e.x + e.y + e.z + e.w;
        q3 += e.x * e.x + e.y * e.y + e.z * e.z + e.w * e.w;
    }
    float s = (s0 + s1) + (s2 + s3);
    float q = (q0 + q1) + (q2 + q3);

    __shared__ float rs[32], rq[32], stat[2];
    __shared__ float sSc[CPG], sSh[CPG];
    #pragma unroll
    for (int off = 16; off > 0; off >>= 1) {
        s += __shfl_xor_sync(0xffffffffu, s, off);
        q += __shfl_xor_sync(0xffffffffu, q, off);
    }
    if ((tid & 31) == 0) { rs[tid >> 5] = s; rq[tid >> 5] = q; }
    __syncthreads();
    if (tid < 32) {
        float ws = rs[tid], wq = rq[tid];
        #pragma unroll
        for (int off = 16; off > 0; off >>= 1) {
            ws += __shfl_xor_sync(0xffffffffu, ws, off);
            wq += __shfl_xor_sync(0xffffffffu, wq, off);
        }
        if (tid == 0) {
            const float inv_n = 1.f / (float)(CPG * HWSZ);
            float mean = ws * inv_n;
            float var  = wq * inv_n - mean * mean;
            stat[0] = mean;
            stat[1] = rsqrtf(var + 1e-5f);
        }
    }
    __syncthreads();
    if (tid < CPG) {
        const float QSC = 0.125f * 1.4426950408889634f;
        float mean = stat[0], rstd = stat[1];
        int c = g * CPG + tid;
        float sc = rstd * w[c];
        float sh = bs[c] - mean * sc;
        if (g % 3 == 1) { sc *= QSC; sh *= QSC; }    // whole group is Q
        sSc[tid] = sc;
        sSh[tid] = sh;
    }
    __syncthreads();

    __half* oh = g_xh + base;
    #pragma unroll
    for (int k = 0; k < 8; k++) {
        int chunk = tid + k * 1024;
        int e = chunk * 8;
        int c = e >> 10;
        float sc = sSc[c], sh = sSh[c];
        float4 v0 = p4[chunk * 2];
        float4 v1 = p4[chunk * 2 + 1];
        uint4 pk;
        pk.x = packh2(v0.x * sc + sh, v0.y * sc + sh);
        pk.y = packh2(v0.z * sc + sh, v0.w * sc + sh);
        pk.z = packh2(v1.x * sc + sh, v1.y * sc + sh);
        pk.w = packh2(v1.z * sc + sh, v1.w * sc + sh);
        *(uint4*)&oh[e] = pk;
    }
}

// ---------------------------------------------------------------------------
// helpers
// ---------------------------------------------------------------------------
__device__ __forceinline__ uint32_t smem_u32(const void* p) {
    uint32_t a;
    asm("{ .reg .u64 t; cvta.to.shared.u64 t, %1; cvt.u32.u64 %0, t; }"
        : "=r"(a) : "l"(p));
    return a;
}
__device__ __forceinline__ void ldsm4(uint32_t* r, uint32_t addr) {
    asm volatile("ldmatrix.sync.aligned.m8n8.x4.shared.b16 {%0,%1,%2,%3}, [%4];"
                 : "=r"(r[0]), "=r"(r[1]), "=r"(r[2]), "=r"(r[3]) : "r"(addr));
}
__device__ __forceinline__ void ldsm4t(uint32_t* r, uint32_t addr) {
    asm volatile("ldmatrix.sync.aligned.m8n8.x4.trans.shared.b16 {%0,%1,%2,%3}, [%4];"
                 : "=r"(r[0]), "=r"(r[1]), "=r"(r[2]), "=r"(r[3]) : "r"(addr));
}
__device__ __forceinline__ void mma16816(float* d, const uint32_t* a,
                                         uint32_t b0, uint32_t b1) {
    asm volatile(
        "mma.sync.aligned.m16n8k16.row.col.f32.f16.f16.f32 "
        "{%0,%1,%2,%3}, {%4,%5,%6,%7}, {%8,%9}, {%0,%1,%2,%3};"
        : "+f"(d[0]), "+f"(d[1]), "+f"(d[2]), "+f"(d[3])
        : "r"(a[0]), "r"(a[1]), "r"(a[2]), "r"(a[3]), "r"(b0), "r"(b1));
}
// ex2 on packed half2 — ONE MUFU warp-instruction per 2 probabilities
__device__ __forceinline__ uint32_t ex2h2(uint32_t x) {
    uint32_t r;
    asm("ex2.approx.f16x2 %0, %1;" : "=r"(r) : "r"(x));
    return r;
}
__device__ __forceinline__ void cp16(uint32_t dst, const void* src) {
    asm volatile("cp.async.cg.shared.global [%0], [%1], 16;"
                 :: "r"(dst), "l"(src) : "memory");
}
__device__ __forceinline__ void cp_commit() {
    asm volatile("cp.async.commit_group;" ::: "memory");
}
template<int N> __device__ __forceinline__ void cp_wait() {
    asm volatile("cp.async.wait_group %0;" :: "n"(N) : "memory");
}

// SMEM layout (bytes):
//   Qs  half[64][136]          @ 0         (17408)
//   3 x { Ks half[64][72] ; Vs half[64][72] }  @ 17408, stride 18432
// Osm float[64][132] (33792B) overlays @0 in the epilogue.
#define QS_OFF   0
#define BUF_OFF  17408
#define BUF_STR  18432
#define SMEM_SZ  72704

// ---------------------------------------------------------------------------
// Kernel B: HMMA flash attention, triple-buffered cp.async, chunk pipeline
// S(p) ; PV(p-1) ; exp(p), with f16x2 MUFU exp (halved MUFU load).
// grid = (8 q-tiles of 128, 64 bh), 256 threads.
// ---------------------------------------------------------------------------
__global__ __launch_bounds__(256, 2)
void attn_mma(float* __restrict__ out) {
    extern __shared__ char smc[];
    float* Osm = (float*)smc;

    const uint32_t sb = smem_u32(smc);
    const int tid = threadIdx.x;
    const int wid = tid >> 5, lane = tid & 31;
    const int qbase = wid * 16;
    const int bh = blockIdx.y, b = bh >> 3, h = bh & 7;
    const int q0 = blockIdx.x * 128;
    const __half* xh = g_xh + ((size_t)b * NC + (size_t)h * 192) * HWSZ;

    // Q prologue: 64 rows x 256B = 1024 chunks of 16B, 4 per thread.
    {
        #pragma unroll
        for (int k = 0; k < 4; k++) {
            int idx = tid + k * 256;
            int row = idx >> 4, ch = idx & 15;
            cp16(sb + QS_OFF + (uint32_t)(row * 272 + ch * 16),
                 xh + (size_t)(64 + row) * HWSZ + q0 + ch * 8);
        }
        cp_commit();
    }
    // Stage K/V tiles 0 and 1 (512 16B-chunks each for K and V; 2/thread).
    #pragma unroll
    for (int t0 = 0; t0 < 2; t0++) {
        uint32_t bufb = sb + BUF_OFF + t0 * BUF_STR;
        #pragma unroll
        for (int k = 0; k < 2; k++) {
            int idx = tid + k * 256;
            int row = idx >> 3, ch = idx & 7;
            cp16(bufb + (uint32_t)(row * 144 + ch * 16),
                 xh + (size_t)row * HWSZ + t0 * 64 + ch * 8);
        }
        #pragma unroll
        for (int k = 0; k < 2; k++) {
            int idx = tid + k * 256;
            int row = idx >> 3, ch = idx & 7;
            cp16(bufb + 9216 + (uint32_t)(row * 144 + ch * 16),
                 xh + (size_t)(128 + row) * HWSZ + t0 * 64 + ch * 8);
        }
        cp_commit();
    }

    cp_wait<2>();          // Q landed
    __syncthreads();

    // ---- Preload Q fragments (persist across all k-tiles) ----
    uint32_t qf[4][4];
    {
        int crow0 = ((lane & 16) >> 1) + (lane & 7);
        int qcol  = qbase + (lane & 8);
        #pragma unroll
        for (int kc = 0; kc < 4; kc++)
            ldsm4t(qf[kc], sb + QS_OFF + (uint32_t)((kc * 16 + crow0) * 136 + qcol) * 2);
    }

    float o[8][4];
    #pragma unroll
    for (int i = 0; i < 8; i++)
        #pragma unroll
        for (int j = 0; j < 4; j++) o[i][j] = 0.f;
    float l0 = 0.f, l1 = 0.f;

    const uint32_t kfo = (uint32_t)(((lane & 8) + (lane & 7)) * 72 + ((lane & 16) >> 1)) * 2;
    const uint32_t vfo = (uint32_t)((((lane & 16) >> 1) + (lane & 7)) * 72 + (lane & 8)) * 2 + 9216;

    for (int kt = 0; kt < 16; kt++) {
        if (kt < 15) cp_wait<1>(); else cp_wait<0>();
        __syncthreads();   // tile kt visible; all warps done reading tile kt-1

        // Prefetch tile kt+2 into buffer (kt+2)%3.
        if (kt + 2 < 16) {
            const int jn = (kt + 2) * 64;
            uint32_t bufb = sb + BUF_OFF + ((kt + 2) % 3) * BUF_STR;
            #pragma unroll
            for (int k = 0; k < 2; k++) {
                int idx = tid + k * 256;
                int row = idx >> 3, ch = idx & 7;
                cp16(bufb + (uint32_t)(row * 144 + ch * 16),
                     xh + (size_t)row * HWSZ + jn + ch * 8);
            }
            #pragma unroll
            for (int k = 0; k < 2; k++) {
                int idx = tid + k * 256;
                int row = idx >> 3, ch = idx & 7;
                cp16(bufb + 9216 + (uint32_t)(row * 144 + ch * 16),
                     xh + (size_t)(128 + row) * HWSZ + jn + ch * 8);
            }
            cp_commit();
        }

        const uint32_t bufb = sb + BUF_OFF + (kt % 3) * BUF_STR;
        const uint32_t kfb = bufb + kfo;
        const uint32_t vfb = bufb + vfo;

        // ---- chunk-pipelined S / exp / PV ----
        uint32_t pprev[4];          // packed P for chunk p-1
        #pragma unroll
        for (int p = 0; p < 4; p++) {
            // S-MMAs for n-chunk p (16 keys)
            float s0[4] = {0.f, 0.f, 0.f, 0.f};
            float s1[4] = {0.f, 0.f, 0.f, 0.f};
            #pragma unroll
            for (int kc = 0; kc < 4; kc++) {
                uint32_t kb[4];
                ldsm4t(kb, kfb + (uint32_t)(kc * 16 * 72 + p * 16) * 2);
                mma16816(s0, qf[kc], kb[0], kb[1]);
                mma16816(s1, qf[kc], kb[2], kb[3]);
            }
            // PV-MMAs for chunk p-1 (independent of the S-MMAs above)
            if (p > 0) {
                const int jc = p - 1;
                #pragma unroll
                for (int vp = 0; vp < 4; vp++) {
                    uint32_t vb[4];
                    ldsm4(vb, vfb + (uint32_t)(vp * 16 * 72 + jc * 16) * 2);
                    mma16816(o[2 * vp],     pprev, vb[0], vb[1]);
                    mma16816(o[2 * vp + 1], pprev, vb[2], vb[3]);
                }
            }
            // exp chunk p: pack S to f16x2 first, then ONE MUFU op per pair
            pprev[0] = ex2h2(packh2(s0[0], s0[1]));
            pprev[1] = ex2h2(packh2(s0[2], s0[3]));
            pprev[2] = ex2h2(packh2(s1[0], s1[1]));
            pprev[3] = ex2h2(packh2(s1[2], s1[3]));
            // row sums: pairwise HADD2 (values <= 2*2^12, no f16 overflow),
            // then widen to f32.
            __half2 u0 = __hadd2(*(__half2*)&pprev[0], *(__half2*)&pprev[2]);
            __half2 u1 = __hadd2(*(__half2*)&pprev[1], *(__half2*)&pprev[3]);
            l0 += __low2float(u0) + __high2float(u0);
            l1 += __low2float(u1) + __high2float(u1);
        }
        // tail: PV for chunk 3
        #pragma unroll
        for (int vp = 0; vp < 4; vp++) {
            uint32_t vb[4];
            ldsm4(vb, vfb + (uint32_t)(vp * 16 * 72 + 3 * 16) * 2);
            mma16816(o[2 * vp],     pprev, vb[0], vb[1]);
            mma16816(o[2 * vp + 1], pprev, vb[2], vb[3]);
        }
    }

    // ---- Epilogue: normalize, stage via SMEM, coalesced store ----
    l0 += __shfl_xor_sync(0xffffffffu, l0, 1);
    l0 += __shfl_xor_sync(0xffffffffu, l0, 2);
    l1 += __shfl_xor_sync(0xffffffffu, l1, 1);
    l1 += __shfl_xor_sync(0xffffffffu, l1, 2);
    float inv0 = 1.f / l0, inv1 = 1.f / l1;

    __syncthreads();       // all warps done with Q/K/V SMEM
    {
        int qa = qbase + (lane >> 2);
        #pragma unroll
        for (int vn = 0; vn < 8; vn++) {
            int vd = vn * 8 + (lane & 3) * 2;
            Osm[vd * 132 + qa]           = o[vn][0] * inv0;
            Osm[(vd + 1) * 132 + qa]     = o[vn][1] * inv0;
            Osm[vd * 132 + qa + 8]       = o[vn][2] * inv1;
            Osm[(vd + 1) * 132 + qa + 8] = o[vn][3] * inv1;
        }
    }
    __syncthreads();

    float* gout = out + ((size_t)(bh * 64)) * HWSZ + q0;
    #pragma unroll
    for (int k = 0; k < 8; k++) {
        int idx = tid + k * 256;
        int vd = idx >> 5, fq = (idx & 31) * 4;
        *(float4*)(gout + (size_t)vd * HWSZ + fq) = *(const float4*)&Osm[vd * 132 + fq];
    }
}

// ---------------------------------------------------------------------------
extern "C" void kernel_launch(void* const* d_in, const int* in_sizes, int n_in,
                              void* d_out, int out_size) {
    const float* x    = (const float*)d_in[0];
    const float* w    = (const float*)d_in[1];
    const float* bias = (const float*)d_in[2];
    float* out = (float*)d_out;

    cudaFuncSetAttribute(attn_mma, cudaFuncAttributeMaxDynamicSharedMemorySize, SMEM_SZ);

    gn_fused_kernel<<<NB * NG, 1024>>>(x, w, bias);
    attn_mma<<<dim3(8, 64), 256, SMEM_SZ>>>(out);
}

// round 13
// speedup vs baseline: 1.0605x; 1.0423x over previous
#include <cuda_runtime.h>
#include <cuda_fp16.h>
#include <cstdint>
#include <math.h>

#define NB   8
#define NC   1536
#define HWSZ 1024
#define NG   24
#define CPG  64

__device__ __half g_xh[(size_t)NB * NC * HWSZ];   // GN-normalized fp16 tensor

// pack two floats into half2 {lo=a, hi=b}
__device__ __forceinline__ uint32_t packh2(float a, float b) {
    uint32_t r;
    asm("cvt.rn.f16x2.f32 %0, %1, %2;" : "=r"(r) : "f"(b), "f"(a));
    return r;
}

// ---------------------------------------------------------------------------
// Kernel A (fused): per-(b,group) stats + fp16 conversion in one pass.
// ---------------------------------------------------------------------------
__global__ __launch_bounds__(1024)
void gn_fused_kernel(const float* __restrict__ x,
                     const float* __restrict__ w,
                     const float* __restrict__ bs) {
    const int b = blockIdx.x / NG;
    const int g = blockIdx.x % NG;
    const int tid = threadIdx.x;
    const size_t base = ((size_t)b * NC + (size_t)g * CPG) * HWSZ;
    const float4* p4 = (const float4*)(x + base);

    float s0 = 0.f, s1 = 0.f, s2 = 0.f, s3 = 0.f;
    float q0 = 0.f, q1 = 0.f, q2 = 0.f, q3 = 0.f;
    #pragma unroll
    for (int k = 0; k < 4; k++) {
        float4 a = p4[tid + (4 * k + 0) * 1024];
        float4 c = p4[tid + (4 * k + 1) * 1024];
        float4 d = p4[tid + (4 * k + 2) * 1024];
        float4 e = p4[tid + (4 * k + 3) * 1024];
        s0 += a.x + a.y + a.z + a.w;
        q0 += a.x * a.x + a.y * a.y + a.z * a.z + a.w * a.w;
        s1 += c.x + c.y + c.z + c.w;
        q1 += c.x * c.x + c.y * c.y + c.z * c.z + c.w * c.w;
        s2 += d.x + d.y + d.z + d.w;
        q2 += d.x * d.x + d.y * d.y + d.z * d.z + d.w * d.w;
        s3 += e.x + e.y + e.z + e.w;
        q3 += e.x * e.x + e.y * e.y + e.z * e.z + e.w * e.w;
    }
    float s = (s0 + s1) + (s2 + s3);
    float q = (q0 + q1) + (q2 + q3);

    __shared__ float rs[32], rq[32], stat[2];
    __shared__ float sSc[CPG], sSh[CPG];
    #pragma unroll
    for (int off = 16; off > 0; off >>= 1) {
        s += __shfl_xor_sync(0xffffffffu, s, off);
        q += __shfl_xor_sync(0xffffffffu, q, off);
    }
    if ((tid & 31) == 0) { rs[tid >> 5] = s; rq[tid >> 5] = q; }
    __syncthreads();
    if (tid < 32) {
        float ws = rs[tid], wq = rq[tid];
        #pragma unroll
        for (int off = 16; off > 0; off >>= 1) {
            ws += __shfl_xor_sync(0xffffffffu, ws, off);
            wq += __shfl_xor_sync(0xffffffffu, wq, off);
        }
        if (tid == 0) {
            const float inv_n = 1.f / (float)(CPG * HWSZ);
            float mean = ws * inv_n;
            float var  = wq * inv_n - mean * mean;
            stat[0] = mean;
            stat[1] = rsqrtf(var + 1e-5f);
        }
    }
    __syncthreads();
    if (tid < CPG) {
        const float QSC = 0.125f * 1.4426950408889634f;
        float mean = stat[0], rstd = stat[1];
        int c = g * CPG + tid;
        float sc = rstd * w[c];
        float sh = bs[c] - mean * sc;
        if (g % 3 == 1) { sc *= QSC; sh *= QSC; }    // whole group is Q
        sSc[tid] = sc;
        sSh[tid] = sh;
    }
    __syncthreads();

    __half* oh = g_xh + base;
    #pragma unroll
    for (int k = 0; k < 8; k++) {
        int chunk = tid + k * 1024;
        int e = chunk * 8;
        int c = e >> 10;
        float sc = sSc[c], sh = sSh[c];
        float4 v0 = p4[chunk * 2];
        float4 v1 = p4[chunk * 2 + 1];
        uint4 pk;
        pk.x = packh2(v0.x * sc + sh, v0.y * sc + sh);
        pk.y = packh2(v0.z * sc + sh, v0.w * sc + sh);
        pk.z = packh2(v1.x * sc + sh, v1.y * sc + sh);
        pk.w = packh2(v1.z * sc + sh, v1.w * sc + sh);
        *(uint4*)&oh[e] = pk;
    }
}

// ---------------------------------------------------------------------------
// helpers
// ---------------------------------------------------------------------------
__device__ __forceinline__ uint32_t smem_u32(const void* p) {
    uint32_t a;
    asm("{ .reg .u64 t; cvta.to.shared.u64 t, %1; cvt.u32.u64 %0, t; }"
        : "=r"(a) : "l"(p));
    return a;
}
__device__ __forceinline__ void ldsm4(uint32_t* r, uint32_t addr) {
    asm volatile("ldmatrix.sync.aligned.m8n8.x4.shared.b16 {%0,%1,%2,%3}, [%4];"
                 : "=r"(r[0]), "=r"(r[1]), "=r"(r[2]), "=r"(r[3]) : "r"(addr));
}
__device__ __forceinline__ void ldsm4t(uint32_t* r, uint32_t addr) {
    asm volatile("ldmatrix.sync.aligned.m8n8.x4.trans.shared.b16 {%0,%1,%2,%3}, [%4];"
                 : "=r"(r[0]), "=r"(r[1]), "=r"(r[2]), "=r"(r[3]) : "r"(addr));
}
__device__ __forceinline__ void mma16816(float* d, const uint32_t* a,
                                         uint32_t b0, uint32_t b1) {
    asm volatile(
        "mma.sync.aligned.m16n8k16.row.col.f32.f16.f16.f32 "
        "{%0,%1,%2,%3}, {%4,%5,%6,%7}, {%8,%9}, {%0,%1,%2,%3};"
        : "+f"(d[0]), "+f"(d[1]), "+f"(d[2]), "+f"(d[3])
        : "r"(a[0]), "r"(a[1]), "r"(a[2]), "r"(a[3]), "r"(b0), "r"(b1));
}
// ex2 on packed half2 — ONE MUFU warp-instruction per 2 probabilities
__device__ __forceinline__ uint32_t ex2h2(uint32_t x) {
    uint32_t r;
    asm("ex2.approx.f16x2 %0, %1;" : "=r"(r) : "r"(x));
    return r;
}
__device__ __forceinline__ void cp16(uint32_t dst, const void* src) {
    asm volatile("cp.async.cg.shared.global [%0], [%1], 16;"
                 :: "r"(dst), "l"(src) : "memory");
}
__device__ __forceinline__ void cp_commit() {
    asm volatile("cp.async.commit_group;" ::: "memory");
}
template<int N> __device__ __forceinline__ void cp_wait() {
    asm volatile("cp.async.wait_group %0;" :: "n"(N) : "memory");
}

// SMEM layout (bytes):
//   Qs  half[64][264]          @ 0         (33792)   rows=chn, 256 q + pad
//   3 x { Ks half[64][72] ; Vs half[64][72] }  @ 33792, stride 18432
// Osm float[64][132] (33792B) overlays Qs in the epilogue.
#define QS_OFF   0
#define BUF_OFF  33792
#define BUF_STR  18432
#define SMEM_SZ  89088

// ---------------------------------------------------------------------------
// Kernel B: HMMA flash attention. Each warp owns 32 q-rows (2 m-tiles) so
// every K/V B-fragment load is amortized over 2x the MMAs (smem crossbar
// traffic per q-row halved). q-tile 256/CTA, grid (4,64) = 256 CTAs = ONE
// wave at occupancy 2. Triple-buffered cp.async K/V.
// ---------------------------------------------------------------------------
__global__ __launch_bounds__(256, 2)
void attn_mma(float* __restrict__ out) {
    extern __shared__ char smc[];
    float* Osm = (float*)smc;

    const uint32_t sb = smem_u32(smc);
    const int tid = threadIdx.x;
    const int wid = tid >> 5, lane = tid & 31;
    const int bh = blockIdx.y;
    const int q0 = blockIdx.x * 256;
    const __half* xh = g_xh + ((size_t)(bh >> 3) * NC + (size_t)(bh & 7) * 192) * HWSZ;

    // Q prologue: 64 rows x 512B = 2048 chunks of 16B, 8 per thread.
    {
        #pragma unroll
        for (int k = 0; k < 8; k++) {
            int idx = tid + k * 256;
            int row = idx >> 5, ch = idx & 31;
            cp16(sb + QS_OFF + (uint32_t)(row * 528 + ch * 16),
                 xh + (size_t)(64 + row) * HWSZ + q0 + ch * 8);
        }
        cp_commit();
    }
    // Stage K/V tiles 0 and 1 (512 16B-chunks each for K and V; 2/thread).
    #pragma unroll
    for (int t0 = 0; t0 < 2; t0++) {
        uint32_t bufb = sb + BUF_OFF + t0 * BUF_STR;
        #pragma unroll
        for (int k = 0; k < 2; k++) {
            int idx = tid + k * 256;
            int row = idx >> 3, ch = idx & 7;
            cp16(bufb + (uint32_t)(row * 144 + ch * 16),
                 xh + (size_t)row * HWSZ + t0 * 64 + ch * 8);
        }
        #pragma unroll
        for (int k = 0; k < 2; k++) {
            int idx = tid + k * 256;
            int row = idx >> 3, ch = idx & 7;
            cp16(bufb + 9216 + (uint32_t)(row * 144 + ch * 16),
                 xh + (size_t)(128 + row) * HWSZ + t0 * 64 + ch * 8);
        }
        cp_commit();
    }

    cp_wait<2>();          // Q landed
    __syncthreads();

    // ---- Preload Q fragments: 2 m-tiles x 4 k-chunks (persist all tiles) ----
    uint32_t qf[2][4][4];
    {
        int crow0 = ((lane & 16) >> 1) + (lane & 7);
        #pragma unroll
        for (int mm = 0; mm < 2; mm++) {
            int qcol = wid * 32 + mm * 16 + (lane & 8);
            #pragma unroll
            for (int kc = 0; kc < 4; kc++)
                ldsm4t(qf[mm][kc],
                       sb + QS_OFF + (uint32_t)((kc * 16 + crow0) * 264 + qcol) * 2);
        }
    }

    float o[2][8][4];
    #pragma unroll
    for (int mm = 0; mm < 2; mm++)
        #pragma unroll
        for (int i = 0; i < 8; i++)
            #pragma unroll
            for (int j = 0; j < 4; j++) o[mm][i][j] = 0.f;
    float l00 = 0.f, l01 = 0.f, l10 = 0.f, l11 = 0.f;

    const uint32_t kfo = (uint32_t)(((lane & 8) + (lane & 7)) * 72 + ((lane & 16) >> 1)) * 2;
    const uint32_t vfo = (uint32_t)((((lane & 16) >> 1) + (lane & 7)) * 72 + (lane & 8)) * 2 + 9216;

    for (int kt = 0; kt < 16; kt++) {
        if (kt < 15) cp_wait<1>(); else cp_wait<0>();
        __syncthreads();   // tile kt visible; all warps done reading tile kt-1

        // Prefetch tile kt+2 into buffer (kt+2)%3.
        if (kt + 2 < 16) {
            const int jn = (kt + 2) * 64;
            uint32_t bufb = sb + BUF_OFF + ((kt + 2) % 3) * BUF_STR;
            #pragma unroll
            for (int k = 0; k < 2; k++) {
                int idx = tid + k * 256;
                int row = idx >> 3, ch = idx & 7;
                cp16(bufb + (uint32_t)(row * 144 + ch * 16),
                     xh + (size_t)row * HWSZ + jn + ch * 8);
            }
            #pragma unroll
            for (int k = 0; k < 2; k++) {
                int idx = tid + k * 256;
                int row = idx >> 3, ch = idx & 7;
                cp16(bufb + 9216 + (uint32_t)(row * 144 + ch * 16),
                     xh + (size_t)(128 + row) * HWSZ + jn + ch * 8);
            }
            cp_commit();
        }

        const uint32_t bufb = sb + BUF_OFF + (kt % 3) * BUF_STR;
        const uint32_t kfb = bufb + kfo;
        const uint32_t vfb = bufb + vfo;

        #pragma unroll
        for (int p = 0; p < 4; p++) {
            // ---- S-MMAs for 16-key chunk p; kb shared by both m-tiles ----
            float s0a[4] = {0.f, 0.f, 0.f, 0.f};
            float s1a[4] = {0.f, 0.f, 0.f, 0.f};
            float s0b[4] = {0.f, 0.f, 0.f, 0.f};
            float s1b[4] = {0.f, 0.f, 0.f, 0.f};
            #pragma unroll
            for (int kc = 0; kc < 4; kc++) {
                uint32_t kb[4];
                ldsm4t(kb, kfb + (uint32_t)(kc * 16 * 72 + p * 16) * 2);
                mma16816(s0a, qf[0][kc], kb[0], kb[1]);
                mma16816(s1a, qf[0][kc], kb[2], kb[3]);
                mma16816(s0b, qf[1][kc], kb[0], kb[1]);
                mma16816(s1b, qf[1][kc], kb[2], kb[3]);
            }
            // ---- exp: f16x2 MUFU ----
            uint32_t pa[4], pb[4];
            pa[0] = ex2h2(packh2(s0a[0], s0a[1]));
            pa[1] = ex2h2(packh2(s0a[2], s0a[3]));
            pa[2] = ex2h2(packh2(s1a[0], s1a[1]));
            pa[3] = ex2h2(packh2(s1a[2], s1a[3]));
            pb[0] = ex2h2(packh2(s0b[0], s0b[1]));
            pb[1] = ex2h2(packh2(s0b[2], s0b[3]));
            pb[2] = ex2h2(packh2(s1b[0], s1b[1]));
            pb[3] = ex2h2(packh2(s1b[2], s1b[3]));
            {
                __half2 u0 = __hadd2(*(__half2*)&pa[0], *(__half2*)&pa[2]);
                __half2 u1 = __hadd2(*(__half2*)&pa[1], *(__half2*)&pa[3]);
                __half2 u2 = __hadd2(*(__half2*)&pb[0], *(__half2*)&pb[2]);
                __half2 u3 = __hadd2(*(__half2*)&pb[1], *(__half2*)&pb[3]);
                l00 += __low2float(u0) + __high2float(u0);
                l01 += __low2float(u1) + __high2float(u1);
                l10 += __low2float(u2) + __high2float(u2);
                l11 += __low2float(u3) + __high2float(u3);
            }
            // ---- PV-MMAs for chunk p; vb shared by both m-tiles ----
            #pragma unroll
            for (int vp = 0; vp < 4; vp++) {
                uint32_t vb[4];
                ldsm4(vb, vfb + (uint32_t)(vp * 16 * 72 + p * 16) * 2);
                mma16816(o[0][2 * vp],     pa, vb[0], vb[1]);
                mma16816(o[0][2 * vp + 1], pa, vb[2], vb[3]);
                mma16816(o[1][2 * vp],     pb, vb[0], vb[1]);
                mma16816(o[1][2 * vp + 1], pb, vb[2], vb[3]);
            }
        }
    }

    // ---- Epilogue ----
    l00 += __shfl_xor_sync(0xffffffffu, l00, 1);
    l00 += __shfl_xor_sync(0xffffffffu, l00, 2);
    l01 += __shfl_xor_sync(0xffffffffu, l01, 1);
    l01 += __shfl_xor_sync(0xffffffffu, l01, 2);
    l10 += __shfl_xor_sync(0xffffffffu, l10, 1);
    l10 += __shfl_xor_sync(0xffffffffu, l10, 2);
    l11 += __shfl_xor_sync(0xffffffffu, l11, 1);
    l11 += __shfl_xor_sync(0xffffffffu, l11, 2);
    float inv[2][2];
    inv[0][0] = 1.f / l00; inv[0][1] = 1.f / l01;
    inv[1][0] = 1.f / l10; inv[1][1] = 1.f / l11;

    __syncthreads();       // all warps done with Q/K/V SMEM

    // Two passes of 128 q-rows each: warps 0-3 hold q 0..127, warps 4-7 hold 128..255.
    #pragma unroll
    for (int hh = 0; hh < 2; hh++) {
        if ((wid >> 2) == hh) {
            int qa = (wid & 3) * 32 + (lane >> 2);
            #pragma unroll
            for (int mm = 0; mm < 2; mm++) {
                int qm = qa + mm * 16;
                #pragma unroll
                for (int vn = 0; vn < 8; vn++) {
                    int vd = vn * 8 + (lane & 3) * 2;
                    Osm[vd * 132 + qm]           = o[mm][vn][0] * inv[mm][0];
                    Osm[(vd + 1) * 132 + qm]     = o[mm][vn][1] * inv[mm][0];
                    Osm[vd * 132 + qm + 8]       = o[mm][vn][2] * inv[mm][1];
                    Osm[(vd + 1) * 132 + qm + 8] = o[mm][vn][3] * inv[mm][1];
                }
            }
        }
        __syncthreads();
        float* gout = out + ((size_t)(bh * 64)) * HWSZ + q0 + hh * 128;
        #pragma unroll
        for (int k = 0; k < 8; k++) {
            int idx = tid + k * 256;
            int vd = idx >> 5, fq = (idx & 31) * 4;
            *(float4*)(gout + (size_t)vd * HWSZ + fq) = *(const float4*)&Osm[vd * 132 + fq];
        }
        if (hh == 0) __syncthreads();
    }
}

// ---------------------------------------------------------------------------
extern "C" void kernel_launch(void* const* d_in, const int* in_sizes, int n_in,
                              void* d_out, int out_size) {
    const float* x    = (const float*)d_in[0];
    const float* w    = (const float*)d_in[1];
    const float* bias = (const float*)d_in[2];
    float* out = (float*)d_out;

    cudaFuncSetAttribute(attn_mma, cudaFuncAttributeMaxDynamicSharedMemorySize, SMEM_SZ);

    gn_fused_kernel<<<NB * NG, 1024>>>(x, w, bias);
    attn_mma<<<dim3(4, 64), 256, SMEM_SZ>>>(out);
}